// round 8
// baseline (speedup 1.0000x reference)
#include <cuda_runtime.h>
#include <cuda_fp16.h>
#include <cstdint>

// ---------------- problem constants ----------------
#define L_LEVELS 16
#define T_SIZE 32768
#define TMASK  32767u
#define P1 2654435761u
#define P2 805459861u
#define MAXN (1 << 20)
#define NBINS 32768
#define BLOCK2 128

// scratch (no cudaMalloc allowed)
__device__ float4 g_tmp[MAXN];    // compacted, unsorted
__device__ float4 g_pts[MAXN];    // morton-sorted
__device__ unsigned g_keys[MAXN];
__device__ int g_hist[NBINS];
__device__ int g_off[NBINS];
__device__ int g_blocksum[64];
__device__ int g_count;
__device__ __half g_tblh[L_LEVELS * T_SIZE * 4];   // 4 MB fp16 table

__device__ __forceinline__ unsigned part5(unsigned x) {
    return ((x & 16u) << 8) | ((x & 8u) << 6) | ((x & 4u) << 4) |
           ((x & 2u) << 2) | (x & 1u);
}

// ---------------- kernel 0: convert table f32 -> fp16 -------------------
__global__ void k_convert(const float* __restrict__ t)
{
    int i = blockIdx.x * blockDim.x + threadIdx.x;
    int total = L_LEVELS * T_SIZE * 4 / 2;
    if (i < total) {
        float2 v = ((const float2*)t)[i];
        ((__half2*)g_tblh)[i] = __floats2half2_rn(v.x, v.y);
    }
}

// ---------------- kernel 1: mask + defaults + compact + histogram ------
__global__ void k_mask_compact(const float* __restrict__ xyz,
                               const float* __restrict__ bmin,
                               const float* __restrict__ bmax,
                               float* __restrict__ out, int N)
{
    int i = blockIdx.x * blockDim.x + threadIdx.x;
    bool inb = false;
    float cx = 0.f, cy = 0.f, cz = 0.f;

    if (i < N) {
        float bx0 = bmin[0], by0 = bmin[1], bz0 = bmin[2];
        float bx1 = bmax[0], by1 = bmax[1], bz1 = bmax[2];
        float x = xyz[3 * i + 0];
        float y = xyz[3 * i + 1];
        float z = xyz[3 * i + 2];
        cx = (x - bx0) / (bx1 - bx0);
        cy = (y - by0) / (by1 - by0);
        cz = (z - bz0) / (bz1 - bz0);
        inb = (cx >= 0.f) & (cx <= 1.f) &
              (cy >= 0.f) & (cy <= 1.f) &
              (cz >= 0.f) & (cz <= 1.f);

        out[i] = inb ? 1.f : 0.f;
        float* dxyz = out + N;
        float* drot = out + (size_t)4 * N;
        dxyz[3 * i + 0] = 0.f;
        dxyz[3 * i + 1] = 0.f;
        dxyz[3 * i + 2] = 0.f;
        drot[4 * i + 0] = 1.f;
        drot[4 * i + 1] = 0.f;
        drot[4 * i + 2] = 0.f;
        drot[4 * i + 3] = 0.f;
    }

    unsigned m = __ballot_sync(0xffffffffu, inb);
    if (inb) {
        int lane = threadIdx.x & 31;
        int leader = __ffs(m) - 1;
        int base = 0;
        if (lane == leader) base = atomicAdd(&g_count, __popc(m));
        base = __shfl_sync(m, base, leader);
        int slot = base + __popc(m & ((1u << lane) - 1u));
        cx = fminf(fmaxf(cx, 0.f), 1.f);
        cy = fminf(fmaxf(cy, 0.f), 1.f);
        cz = fminf(fmaxf(cz, 0.f), 1.f);
        g_tmp[slot] = make_float4(cx, cy, cz, __int_as_float(i));
        unsigned qx = min(31u, (unsigned)(cx * 32.f));
        unsigned qy = min(31u, (unsigned)(cy * 32.f));
        unsigned qz = min(31u, (unsigned)(cz * 32.f));
        unsigned key = part5(qx) | (part5(qy) << 1) | (part5(qz) << 2);
        g_keys[slot] = key;
        atomicAdd(&g_hist[key], 1);
    }
}

// ---------------- scan phase A: 64 blocks, local scan of 512 bins -------
__global__ void k_scanA()
{
    __shared__ int wsum[16];
    int b = blockIdx.x;
    int tid = threadIdx.x;            // 128 threads, 4 bins each
    int base = b * 512 + tid * 4;
    int4 c = *(const int4*)&g_hist[base];
    int s = c.x + c.y + c.z + c.w;

    int lane = tid & 31, wid = tid >> 5;
    int v = s;
    #pragma unroll
    for (int d = 1; d < 32; d <<= 1) {
        int t = __shfl_up_sync(0xffffffffu, v, d);
        if (lane >= d) v += t;
    }
    if (lane == 31) wsum[wid] = v;
    __syncthreads();
    if (tid == 0) {
        int acc = 0;
        #pragma unroll
        for (int w = 0; w < 4; w++) { int t = wsum[w]; wsum[w] = acc; acc += t; }
        g_blocksum[b] = acc;
    }
    __syncthreads();
    int excl = v - s + wsum[wid];
    int4 o;
    o.x = excl; o.y = excl + c.x; o.z = o.y + c.y; o.w = o.z + c.z;
    *(int4*)&g_off[base] = o;
}

// ---------------- scan phase B: 64 blocks add block prefixes ------------
__global__ void k_scanB()
{
    __shared__ int pre;
    int b = blockIdx.x;               // 64 blocks x 512 bins
    int tid = threadIdx.x;            // 128 threads
    if (tid == 0) {
        int acc = 0;
        for (int i = 0; i < b; i++) acc += g_blocksum[i];
        pre = acc;
    }
    __syncthreads();
    int add = pre;
    int4 v = *(int4*)&g_off[b * 512 + tid * 4];
    v.x += add; v.y += add; v.z += add; v.w += add;
    *(int4*)&g_off[b * 512 + tid * 4] = v;
}

// ---------------- scatter into sorted order -----------------------------
__global__ void k_scatter()
{
    int cnt = g_count;
    for (int i = blockIdx.x * blockDim.x + threadIdx.x; i < cnt;
         i += gridDim.x * blockDim.x) {
        float4 p = g_tmp[i];
        unsigned key = g_keys[i];
        int pos = atomicAdd(&g_off[key], 1);
        g_pts[pos] = p;
    }
}

// ---------------- smem layout (float offsets) ---------------------------
// Weight halves bank-staggered: odd-half base byte % 128 == 16, so the
// pair's two LDS.128 per step land in one wavefront.
#define OW0A 0        // w0[:, 0:32]  [64][32]
#define OW0B 2052     // w0[:,32:64]  (byte 8208 % 128 = 16)
#define OW1A 4128     // w1[:, 0:32]  (byte 16512 % 128 = 0)
#define OW1B 6180     // w1[:,32:64]  (byte 24720 % 128 = 16)
#define OW2  8256     // w2 [64][8]
#define OACT 8768     // acts/enc: [64 rows][128 pt cols]
#define SMEM_BYTES ((OACT + 64 * BLOCK2) * 4)   // 67840

// ---------------- kernel 2: encode + pair-shared MLP --------------------
__global__ __launch_bounds__(BLOCK2, 3)
void k_encode_mlp(const float* __restrict__ w0,
                  const float* __restrict__ w1,
                  const float* __restrict__ w2,
                  float* __restrict__ out, int N)
{
    extern __shared__ float sf[];
    int tid = threadIdx.x;

    // stage weight halves
    for (int idx = tid; idx < 4096; idx += BLOCK2) {
        int i = idx >> 6, j = idx & 63;
        int d0 = (j < 32) ? (OW0A + i * 32 + j) : (OW0B + i * 32 + j - 32);
        sf[d0] = w0[idx];
        int d1 = (j < 32) ? (OW1A + i * 32 + j) : (OW1B + i * 32 + j - 32);
        sf[d1] = w1[idx];
    }
    for (int idx = tid; idx < 512; idx += BLOCK2)
        sf[OW2 + idx] = w2[idx];
    __syncthreads();

    int cnt = g_count;
    int ntiles = (cnt + BLOCK2 - 1) / BLOCK2;
    if ((int)blockIdx.x >= ntiles) return;

    int h  = tid & 1;          // output-half owner
    int p0 = tid & ~1;         // pair's even point column
    const float4* wA0 = (const float4*)(sf + (h ? OW0B : OW0A));
    const float4* wA1 = (const float4*)(sf + (h ? OW1B : OW1A));
    const float4* w2p = (const float4*)(sf + OW2);
    float* sact = sf + OACT;

    const uint2* tbl = (const uint2*)g_tblh;
    float* dxyz = out + N;
    float* drot = out + (size_t)4 * N;

    for (int tile = blockIdx.x; tile < ntiles; tile += gridDim.x) {
        int slot = tile * BLOCK2 + tid;
        bool act = slot < cnt;
        float4 p = act ? g_pts[slot] : make_float4(0.f, 0.f, 0.f, 0.f);
        float cx = p.x, cy = p.y, cz = p.z;
        int ipt = __float_as_int(p.w);

        // ---- encode own point -> sact rows 4l+f, col tid ----
        float sc = 16.f;
        #pragma unroll 1
        for (int l = 0; l < L_LEVELS; l++) {
            float a0 = 0.f, a1 = 0.f, a2 = 0.f, a3 = 0.f;
            if (act) {
                float px = cx * sc, py = cy * sc, pz = cz * sc;
                float fx = floorf(px), fy = floorf(py), fz = floorf(pz);
                float tx = px - fx, ty = py - fy, tz = pz - fz;
                unsigned ux = (unsigned)fx, uy = (unsigned)fy, uz = (unsigned)fz;
                unsigned hx0 = ux,      hx1 = ux + 1u;
                unsigned hy0 = uy * P1, hy1 = hy0 + P1;
                unsigned hz0 = uz * P2, hz1 = hz0 + P2;
                unsigned base = (unsigned)l * T_SIZE;
                float wxv[2] = {1.f - tx, tx};
                float wyv[2] = {1.f - ty, ty};
                float wzv[2] = {1.f - tz, tz};
                #pragma unroll
                for (int c = 0; c < 8; c++) {
                    unsigned hx = (c & 4) ? hx1 : hx0;
                    unsigned hy = (c & 2) ? hy1 : hy0;
                    unsigned hz = (c & 1) ? hz1 : hz0;
                    unsigned idx = (hx ^ hy ^ hz) & TMASK;
                    uint2 raw = __ldg(tbl + (base + idx));
                    __half2 q01 = *reinterpret_cast<__half2*>(&raw.x);
                    __half2 q23 = *reinterpret_cast<__half2*>(&raw.y);
                    float2 f01 = __half22float2(q01);
                    float2 f23 = __half22float2(q23);
                    float w = wxv[(c >> 2) & 1] * wyv[(c >> 1) & 1] * wzv[c & 1];
                    a0 += w * f01.x; a1 += w * f01.y;
                    a2 += w * f23.x; a3 += w * f23.y;
                }
            }
            sact[(4 * l + 0) * BLOCK2 + tid] = a0;
            sact[(4 * l + 1) * BLOCK2 + tid] = a1;
            sact[(4 * l + 2) * BLOCK2 + tid] = a2;
            sact[(4 * l + 3) * BLOCK2 + tid] = a3;
            sc *= 2.f;
        }
        __syncwarp();

        // ---- layer 1: 32-out half for BOTH pair points ----
        float hA[32], hB[32];
        #pragma unroll
        for (int j = 0; j < 32; j++) { hA[j] = 0.f; hB[j] = 0.f; }
        #pragma unroll 4
        for (int i = 0; i < 64; i++) {
            float2 e = *(const float2*)&sact[i * BLOCK2 + p0];
            const float4* wr = wA0 + i * 8;
            #pragma unroll
            for (int jj = 0; jj < 8; jj++) {
                float4 w4 = wr[jj];
                hA[4*jj+0] += e.x * w4.x; hB[4*jj+0] += e.y * w4.x;
                hA[4*jj+1] += e.x * w4.y; hB[4*jj+1] += e.y * w4.y;
                hA[4*jj+2] += e.x * w4.z; hB[4*jj+2] += e.y * w4.z;
                hA[4*jj+3] += e.x * w4.w; hB[4*jj+3] += e.y * w4.w;
            }
        }
        __syncwarp();
        #pragma unroll
        for (int j = 0; j < 32; j++) {
            float2 s;
            s.x = fmaxf(hA[j], 0.f);
            s.y = fmaxf(hB[j], 0.f);
            *(float2*)&sact[(h * 32 + j) * BLOCK2 + p0] = s;
        }
        __syncwarp();

        // ---- layer 2: same pattern ----
        #pragma unroll
        for (int j = 0; j < 32; j++) { hA[j] = 0.f; hB[j] = 0.f; }
        #pragma unroll 4
        for (int i = 0; i < 64; i++) {
            float2 e = *(const float2*)&sact[i * BLOCK2 + p0];
            const float4* wr = wA1 + i * 8;
            #pragma unroll
            for (int jj = 0; jj < 8; jj++) {
                float4 w4 = wr[jj];
                hA[4*jj+0] += e.x * w4.x; hB[4*jj+0] += e.y * w4.x;
                hA[4*jj+1] += e.x * w4.y; hB[4*jj+1] += e.y * w4.y;
                hA[4*jj+2] += e.x * w4.z; hB[4*jj+2] += e.y * w4.z;
                hA[4*jj+3] += e.x * w4.w; hB[4*jj+3] += e.y * w4.w;
            }
        }
        __syncwarp();
        #pragma unroll
        for (int j = 0; j < 32; j++) {
            float2 s;
            s.x = fmaxf(hA[j], 0.f);
            s.y = fmaxf(hB[j], 0.f);
            *(float2*)&sact[(h * 32 + j) * BLOCK2 + p0] = s;
        }
        __syncwarp();

        // ---- layer 3: 4-output half for both points ----
        float oA[4] = {0.f, 0.f, 0.f, 0.f};
        float oB[4] = {0.f, 0.f, 0.f, 0.f};
        #pragma unroll 8
        for (int i = 0; i < 64; i++) {
            float2 e = *(const float2*)&sact[i * BLOCK2 + p0];
            float4 w4 = w2p[i * 2 + h];
            oA[0] += e.x * w4.x; oB[0] += e.y * w4.x;
            oA[1] += e.x * w4.y; oB[1] += e.y * w4.y;
            oA[2] += e.x * w4.z; oB[2] += e.y * w4.z;
            oA[3] += e.x * w4.w; oB[3] += e.y * w4.w;
        }

        // partner's original point index + active flag
        int ipt2 = __shfl_xor_sync(0xffffffffu, ipt, 1);
        bool act2 = (tile * BLOCK2 + (tid ^ 1)) < cnt;
        // even thread: own point = pair-even (oA); odd: own = pair-odd (oB)
        int iE = h ? ipt2 : ipt;      bool aE = h ? act2 : act;   // even point
        int iO = h ? ipt  : ipt2;     bool aO = h ? act  : act2;  // odd point

        if (h == 0) {
            // outputs 0-3: d_xyz[0..2], d_rot[0]
            if (aE) {
                dxyz[3 * iE + 0] = oA[0];
                dxyz[3 * iE + 1] = oA[1];
                dxyz[3 * iE + 2] = oA[2];
                drot[4 * iE + 0] = oA[3];
            }
            if (aO) {
                dxyz[3 * iO + 0] = oB[0];
                dxyz[3 * iO + 1] = oB[1];
                dxyz[3 * iO + 2] = oB[2];
                drot[4 * iO + 0] = oB[3];
            }
        } else {
            // outputs 4-6: d_rot[1..3] (output 7 unused)
            if (aE) {
                drot[4 * iE + 1] = oA[0];
                drot[4 * iE + 2] = oA[1];
                drot[4 * iE + 3] = oA[2];
            }
            if (aO) {
                drot[4 * iO + 1] = oB[0];
                drot[4 * iO + 2] = oB[1];
                drot[4 * iO + 3] = oB[2];
            }
        }
        __syncwarp();   // layer-3 reads done before next tile's enc writes
    }
}

// ---------------- launch ----------------
extern "C" void kernel_launch(void* const* d_in, const int* in_sizes, int n_in,
                              void* d_out, int out_size)
{
    const float* xyz   = (const float*)d_in[0];
    const float* bmin  = (const float*)d_in[1];
    const float* bmax  = (const float*)d_in[2];
    const float* table = (const float*)d_in[3];
    const float* w0    = (const float*)d_in[4];
    const float* w1    = (const float*)d_in[5];
    const float* w2    = (const float*)d_in[6];
    int N = in_sizes[0] / 3;
    float* out = (float*)d_out;

    void* cptr = nullptr;
    cudaGetSymbolAddress(&cptr, g_count);
    cudaMemsetAsync(cptr, 0, sizeof(int), 0);
    void* hptr = nullptr;
    cudaGetSymbolAddress(&hptr, g_hist);
    cudaMemsetAsync(hptr, 0, NBINS * sizeof(int), 0);

    int nconv = L_LEVELS * T_SIZE * 4 / 2;
    k_convert<<<(nconv + 255) / 256, 256>>>(table);

    int grid1 = (N + 255) / 256;
    k_mask_compact<<<grid1, 256>>>(xyz, bmin, bmax, out, N);
    k_scanA<<<64, 128>>>();
    k_scanB<<<64, 128>>>();
    k_scatter<<<512, 256>>>();

    cudaFuncSetAttribute(k_encode_mlp,
                         cudaFuncAttributeMaxDynamicSharedMemorySize, SMEM_BYTES);
    k_encode_mlp<<<444, BLOCK2, SMEM_BYTES>>>(w0, w1, w2, out, N);
}

// round 9
// speedup vs baseline: 1.1490x; 1.1490x over previous
#include <cuda_runtime.h>
#include <cuda_fp16.h>
#include <cstdint>

// ---------------- problem constants ----------------
#define L_LEVELS 16
#define T_SIZE 32768
#define TMASK  32767u
#define P1 2654435761u
#define P2 805459861u
#define MAXN (1 << 20)
#define NBINS 32768
#define BLOCK2 128

// scratch (no cudaMalloc allowed)
__device__ float4 g_tmp[MAXN];    // compacted, unsorted
__device__ float4 g_pts[MAXN];    // morton-sorted
__device__ unsigned g_keys[MAXN];
__device__ int g_hist[NBINS];
__device__ int g_off[NBINS];
__device__ int g_blocksum[64];
__device__ int g_count;
__device__ __half g_tblh[L_LEVELS * T_SIZE * 4];   // 4 MB fp16 table

__device__ __forceinline__ unsigned part5(unsigned x) {
    return ((x & 16u) << 8) | ((x & 8u) << 6) | ((x & 4u) << 4) |
           ((x & 2u) << 2) | (x & 1u);
}

// ---------------- kernel 0: convert table f32 -> fp16 -------------------
__global__ void k_convert(const float* __restrict__ t)
{
    int i = blockIdx.x * blockDim.x + threadIdx.x;
    int total = L_LEVELS * T_SIZE * 4 / 2;
    if (i < total) {
        float2 v = ((const float2*)t)[i];
        ((__half2*)g_tblh)[i] = __floats2half2_rn(v.x, v.y);
    }
}

// ---------------- kernel 1: mask + defaults + compact + histogram ------
__global__ void k_mask_compact(const float* __restrict__ xyz,
                               const float* __restrict__ bmin,
                               const float* __restrict__ bmax,
                               float* __restrict__ out, int N)
{
    int i = blockIdx.x * blockDim.x + threadIdx.x;
    bool inb = false;
    float cx = 0.f, cy = 0.f, cz = 0.f;

    if (i < N) {
        float bx0 = bmin[0], by0 = bmin[1], bz0 = bmin[2];
        float bx1 = bmax[0], by1 = bmax[1], bz1 = bmax[2];
        float x = xyz[3 * i + 0];
        float y = xyz[3 * i + 1];
        float z = xyz[3 * i + 2];
        cx = (x - bx0) / (bx1 - bx0);
        cy = (y - by0) / (by1 - by0);
        cz = (z - bz0) / (bz1 - bz0);
        inb = (cx >= 0.f) & (cx <= 1.f) &
              (cy >= 0.f) & (cy <= 1.f) &
              (cz >= 0.f) & (cz <= 1.f);

        out[i] = inb ? 1.f : 0.f;
        float* dxyz = out + N;
        float* drot = out + (size_t)4 * N;
        dxyz[3 * i + 0] = 0.f;
        dxyz[3 * i + 1] = 0.f;
        dxyz[3 * i + 2] = 0.f;
        drot[4 * i + 0] = 1.f;
        drot[4 * i + 1] = 0.f;
        drot[4 * i + 2] = 0.f;
        drot[4 * i + 3] = 0.f;
    }

    unsigned m = __ballot_sync(0xffffffffu, inb);
    if (inb) {
        int lane = threadIdx.x & 31;
        int leader = __ffs(m) - 1;
        int base = 0;
        if (lane == leader) base = atomicAdd(&g_count, __popc(m));
        base = __shfl_sync(m, base, leader);
        int slot = base + __popc(m & ((1u << lane) - 1u));
        cx = fminf(fmaxf(cx, 0.f), 1.f);
        cy = fminf(fmaxf(cy, 0.f), 1.f);
        cz = fminf(fmaxf(cz, 0.f), 1.f);
        g_tmp[slot] = make_float4(cx, cy, cz, __int_as_float(i));
        unsigned qx = min(31u, (unsigned)(cx * 32.f));
        unsigned qy = min(31u, (unsigned)(cy * 32.f));
        unsigned qz = min(31u, (unsigned)(cz * 32.f));
        unsigned key = part5(qx) | (part5(qy) << 1) | (part5(qz) << 2);
        g_keys[slot] = key;
        atomicAdd(&g_hist[key], 1);
    }
}

// ---------------- scan phase A: 64 blocks, local scan of 512 bins -------
__global__ void k_scanA()
{
    __shared__ int wsum[16];
    int b = blockIdx.x;
    int tid = threadIdx.x;            // 128 threads, 4 bins each
    int base = b * 512 + tid * 4;
    int4 c = *(const int4*)&g_hist[base];
    int s = c.x + c.y + c.z + c.w;

    int lane = tid & 31, wid = tid >> 5;
    int v = s;
    #pragma unroll
    for (int d = 1; d < 32; d <<= 1) {
        int t = __shfl_up_sync(0xffffffffu, v, d);
        if (lane >= d) v += t;
    }
    if (lane == 31) wsum[wid] = v;
    __syncthreads();
    if (tid == 0) {
        int acc = 0;
        #pragma unroll
        for (int w = 0; w < 4; w++) { int t = wsum[w]; wsum[w] = acc; acc += t; }
        g_blocksum[b] = acc;
    }
    __syncthreads();
    int excl = v - s + wsum[wid];
    int4 o;
    o.x = excl; o.y = excl + c.x; o.z = o.y + c.y; o.w = o.z + c.z;
    *(int4*)&g_off[base] = o;
}

// ---------------- scan phase B: 64 blocks add block prefixes ------------
__global__ void k_scanB()
{
    __shared__ int pre;
    int b = blockIdx.x;
    int tid = threadIdx.x;            // 128 threads
    if (tid == 0) {
        int acc = 0;
        for (int i = 0; i < b; i++) acc += g_blocksum[i];
        pre = acc;
    }
    __syncthreads();
    int add = pre;
    int4 v = *(int4*)&g_off[b * 512 + tid * 4];
    v.x += add; v.y += add; v.z += add; v.w += add;
    *(int4*)&g_off[b * 512 + tid * 4] = v;
}

// ---------------- scatter into sorted order -----------------------------
__global__ void k_scatter()
{
    int cnt = g_count;
    for (int i = blockIdx.x * blockDim.x + threadIdx.x; i < cnt;
         i += gridDim.x * blockDim.x) {
        float4 p = g_tmp[i];
        unsigned key = g_keys[i];
        int pos = atomicAdd(&g_off[key], 1);
        g_pts[pos] = p;
    }
}

// ---------------- kernel 2: pipelined encode + MLP ----------------------
// smem: [w0 4096][w1 4096][w2 512][act 64*BLOCK2]
__global__ __launch_bounds__(BLOCK2, 3)
void k_encode_mlp(const float* __restrict__ w0,
                  const float* __restrict__ w1,
                  const float* __restrict__ w2,
                  float* __restrict__ out, int N)
{
    extern __shared__ float sm[];
    float* sw0  = sm;            // 4096 floats
    float* sw1  = sm + 4096;     // 4096 floats
    float* sw2  = sm + 8192;     // 512 floats
    float* sact = sm + 8704;     // 64 * BLOCK2 floats

    int tid = threadIdx.x;
    int cnt = g_count;
    if ((int)(blockIdx.x * BLOCK2) >= cnt) return;

    for (int k = tid; k < 4096 / 4; k += BLOCK2)
        ((float4*)sw0)[k] = ((const float4*)w0)[k];
    for (int k = tid; k < 4096 / 4; k += BLOCK2)
        ((float4*)sw1)[k] = ((const float4*)w1)[k];
    for (int k = tid; k < 512 / 4; k += BLOCK2)
        ((float4*)sw2)[k] = ((const float4*)w2)[k];
    __syncthreads();

    const uint2* tbl = (const uint2*)g_tblh;
    float* dxyz = out + N;
    float* drot = out + (size_t)4 * N;

    for (int slot = blockIdx.x * BLOCK2 + tid; slot < cnt;
         slot += gridDim.x * BLOCK2) {
        float4 p = g_pts[slot];
        float cx = p.x, cy = p.y, cz = p.z;
        int ipt = __float_as_int(p.w);

        float h[64];
        #pragma unroll
        for (int j = 0; j < 64; j++) h[j] = 0.f;

        // ---- pipelined encode: issue level-l loads, FMA level-(l-1) ----
        uint2 raw[8];          // pending corner data
        float cw[8];           // pending corner weights

        // prologue: issue loads for level 0
        {
            float px = cx * 16.f, py = cy * 16.f, pz = cz * 16.f;
            float fx = floorf(px), fy = floorf(py), fz = floorf(pz);
            float tx = px - fx, ty = py - fy, tz = pz - fz;
            unsigned ux = (unsigned)fx, uy = (unsigned)fy, uz = (unsigned)fz;
            unsigned hx0 = ux,      hx1 = ux + 1u;
            unsigned hy0 = uy * P1, hy1 = hy0 + P1;
            unsigned hz0 = uz * P2, hz1 = hz0 + P2;
            float wxv[2] = {1.f - tx, tx};
            float wyv[2] = {1.f - ty, ty};
            float wzv[2] = {1.f - tz, tz};
            #pragma unroll
            for (int c = 0; c < 8; c++) {
                unsigned hx = (c & 4) ? hx1 : hx0;
                unsigned hy = (c & 2) ? hy1 : hy0;
                unsigned hz = (c & 1) ? hz1 : hz0;
                unsigned idx = (hx ^ hy ^ hz) & TMASK;
                raw[c] = __ldg(tbl + idx);
                cw[c] = wxv[(c >> 2) & 1] * wyv[(c >> 1) & 1] * wzv[c & 1];
            }
        }

        float sc = 32.f;   // scale for level 1 (next to issue)
        #pragma unroll 1
        for (int l = 0; l < L_LEVELS; l++) {
            // 1) consume pending loads -> a0..a3 (frees raw[])
            float a0 = 0.f, a1 = 0.f, a2 = 0.f, a3 = 0.f;
            #pragma unroll
            for (int c = 0; c < 8; c++) {
                __half2 q01 = *reinterpret_cast<__half2*>(&raw[c].x);
                __half2 q23 = *reinterpret_cast<__half2*>(&raw[c].y);
                float2 f01 = __half22float2(q01);
                float2 f23 = __half22float2(q23);
                float w = cw[c];
                a0 += w * f01.x; a1 += w * f01.y;
                a2 += w * f23.x; a3 += w * f23.y;
            }

            // 2) issue next level's loads (covered by the FMA block below)
            if (l + 1 < L_LEVELS) {
                float px = cx * sc, py = cy * sc, pz = cz * sc;
                float fx = floorf(px), fy = floorf(py), fz = floorf(pz);
                float tx = px - fx, ty = py - fy, tz = pz - fz;
                unsigned ux = (unsigned)fx, uy = (unsigned)fy, uz = (unsigned)fz;
                unsigned hx0 = ux,      hx1 = ux + 1u;
                unsigned hy0 = uy * P1, hy1 = hy0 + P1;
                unsigned hz0 = uz * P2, hz1 = hz0 + P2;
                unsigned base = (unsigned)(l + 1) * T_SIZE;
                float wxv[2] = {1.f - tx, tx};
                float wyv[2] = {1.f - ty, ty};
                float wzv[2] = {1.f - tz, tz};
                #pragma unroll
                for (int c = 0; c < 8; c++) {
                    unsigned hx = (c & 4) ? hx1 : hx0;
                    unsigned hy = (c & 2) ? hy1 : hy0;
                    unsigned hz = (c & 1) ? hz1 : hz0;
                    unsigned idx = (hx ^ hy ^ hz) & TMASK;
                    raw[c] = __ldg(tbl + (base + idx));
                    cw[c] = wxv[(c >> 2) & 1] * wyv[(c >> 1) & 1] * wzv[c & 1];
                }
                sc *= 2.f;
            }

            // 3) layer-1 FMA block for level l's features
            float av[4] = {a0, a1, a2, a3};
            #pragma unroll
            for (int f = 0; f < 4; f++) {
                const float4* wr = (const float4*)(sw0 + ((l * 4 + f) << 6));
                float a = av[f];
                #pragma unroll
                for (int jj = 0; jj < 16; jj++) {
                    float4 wv = wr[jj];
                    h[4 * jj + 0] += a * wv.x;
                    h[4 * jj + 1] += a * wv.y;
                    h[4 * jj + 2] += a * wv.z;
                    h[4 * jj + 3] += a * wv.w;
                }
            }
        }

        #pragma unroll
        for (int j = 0; j < 64; j++)
            sact[j * BLOCK2 + tid] = fmaxf(h[j], 0.f);

        #pragma unroll
        for (int j = 0; j < 64; j++) h[j] = 0.f;
        #pragma unroll 4
        for (int i = 0; i < 64; i++) {
            float v = sact[i * BLOCK2 + tid];
            const float4* wr = (const float4*)(sw1 + (i << 6));
            #pragma unroll
            for (int jj = 0; jj < 16; jj++) {
                float4 wv = wr[jj];
                h[4 * jj + 0] += v * wv.x;
                h[4 * jj + 1] += v * wv.y;
                h[4 * jj + 2] += v * wv.z;
                h[4 * jj + 3] += v * wv.w;
            }
        }
        #pragma unroll
        for (int j = 0; j < 64; j++)
            sact[j * BLOCK2 + tid] = fmaxf(h[j], 0.f);

        float o[8];
        #pragma unroll
        for (int k = 0; k < 8; k++) o[k] = 0.f;
        #pragma unroll 8
        for (int i = 0; i < 64; i++) {
            float v = sact[i * BLOCK2 + tid];
            const float4* wr = (const float4*)(sw2 + (i << 3));
            float4 wa = wr[0], wb = wr[1];
            o[0] += v * wa.x; o[1] += v * wa.y; o[2] += v * wa.z; o[3] += v * wa.w;
            o[4] += v * wb.x; o[5] += v * wb.y; o[6] += v * wb.z; o[7] += v * wb.w;
        }

        dxyz[3 * ipt + 0] = o[0];
        dxyz[3 * ipt + 1] = o[1];
        dxyz[3 * ipt + 2] = o[2];
        drot[4 * ipt + 0] = o[3];
        drot[4 * ipt + 1] = o[4];
        drot[4 * ipt + 2] = o[5];
        drot[4 * ipt + 3] = o[6];
    }
}

// ---------------- launch ----------------
extern "C" void kernel_launch(void* const* d_in, const int* in_sizes, int n_in,
                              void* d_out, int out_size)
{
    const float* xyz   = (const float*)d_in[0];
    const float* bmin  = (const float*)d_in[1];
    const float* bmax  = (const float*)d_in[2];
    const float* table = (const float*)d_in[3];
    const float* w0    = (const float*)d_in[4];
    const float* w1    = (const float*)d_in[5];
    const float* w2    = (const float*)d_in[6];
    int N = in_sizes[0] / 3;
    float* out = (float*)d_out;

    void* cptr = nullptr;
    cudaGetSymbolAddress(&cptr, g_count);
    cudaMemsetAsync(cptr, 0, sizeof(int), 0);
    void* hptr = nullptr;
    cudaGetSymbolAddress(&hptr, g_hist);
    cudaMemsetAsync(hptr, 0, NBINS * sizeof(int), 0);

    int nconv = L_LEVELS * T_SIZE * 4 / 2;
    k_convert<<<(nconv + 255) / 256, 256>>>(table);

    int grid1 = (N + 255) / 256;
    k_mask_compact<<<grid1, 256>>>(xyz, bmin, bmax, out, N);
    k_scanA<<<64, 128>>>();
    k_scanB<<<64, 128>>>();
    k_scatter<<<512, 256>>>();

    int smem = (8704 + 64 * BLOCK2) * (int)sizeof(float);  // 67584 B
    cudaFuncSetAttribute(k_encode_mlp,
                         cudaFuncAttributeMaxDynamicSharedMemorySize, smem);
    k_encode_mlp<<<444, BLOCK2, smem>>>(w0, w1, w2, out, N);
}

// round 10
// speedup vs baseline: 1.1718x; 1.0198x over previous
#include <cuda_runtime.h>
#include <cuda_fp16.h>
#include <cstdint>

// ---------------- problem constants ----------------
#define L_LEVELS 16
#define T_SIZE 32768
#define TMASK  32767u
#define P1 2654435761u
#define P2 805459861u
#define MAXN (1 << 20)
#define NBINS 32768
#define BLOCK2 128

// scratch (no cudaMalloc allowed)
__device__ float4 g_tmp[MAXN];    // compacted, unsorted
__device__ float4 g_pts[MAXN];    // morton-sorted
__device__ unsigned g_keys[MAXN];
__device__ int g_hist[NBINS];
__device__ int g_off[NBINS];
__device__ int g_blocksum[64];
__device__ int g_count;
__device__ __half g_tblh[L_LEVELS * T_SIZE * 4];   // 4 MB fp16 table

__device__ __forceinline__ unsigned part5(unsigned x) {
    return ((x & 16u) << 8) | ((x & 8u) << 6) | ((x & 4u) << 4) |
           ((x & 2u) << 2) | (x & 1u);
}

// ---------------- kernel 0: convert table f32 -> fp16 -------------------
__global__ void k_convert(const float* __restrict__ t)
{
    int i = blockIdx.x * blockDim.x + threadIdx.x;
    int total = L_LEVELS * T_SIZE * 4 / 2;
    if (i < total) {
        float2 v = ((const float2*)t)[i];
        ((__half2*)g_tblh)[i] = __floats2half2_rn(v.x, v.y);
    }
}

// ---------------- kernel 1: mask + defaults + compact + histogram ------
__global__ void k_mask_compact(const float* __restrict__ xyz,
                               const float* __restrict__ bmin,
                               const float* __restrict__ bmax,
                               float* __restrict__ out, int N)
{
    int i = blockIdx.x * blockDim.x + threadIdx.x;
    bool inb = false;
    float cx = 0.f, cy = 0.f, cz = 0.f;

    if (i < N) {
        float bx0 = bmin[0], by0 = bmin[1], bz0 = bmin[2];
        float bx1 = bmax[0], by1 = bmax[1], bz1 = bmax[2];
        float x = xyz[3 * i + 0];
        float y = xyz[3 * i + 1];
        float z = xyz[3 * i + 2];
        cx = (x - bx0) / (bx1 - bx0);
        cy = (y - by0) / (by1 - by0);
        cz = (z - bz0) / (bz1 - bz0);
        inb = (cx >= 0.f) & (cx <= 1.f) &
              (cy >= 0.f) & (cy <= 1.f) &
              (cz >= 0.f) & (cz <= 1.f);

        out[i] = inb ? 1.f : 0.f;
        float* dxyz = out + N;
        float* drot = out + (size_t)4 * N;
        dxyz[3 * i + 0] = 0.f;
        dxyz[3 * i + 1] = 0.f;
        dxyz[3 * i + 2] = 0.f;
        drot[4 * i + 0] = 1.f;
        drot[4 * i + 1] = 0.f;
        drot[4 * i + 2] = 0.f;
        drot[4 * i + 3] = 0.f;
    }

    unsigned m = __ballot_sync(0xffffffffu, inb);
    if (inb) {
        int lane = threadIdx.x & 31;
        int leader = __ffs(m) - 1;
        int base = 0;
        if (lane == leader) base = atomicAdd(&g_count, __popc(m));
        base = __shfl_sync(m, base, leader);
        int slot = base + __popc(m & ((1u << lane) - 1u));
        cx = fminf(fmaxf(cx, 0.f), 1.f);
        cy = fminf(fmaxf(cy, 0.f), 1.f);
        cz = fminf(fmaxf(cz, 0.f), 1.f);
        g_tmp[slot] = make_float4(cx, cy, cz, __int_as_float(i));
        unsigned qx = min(31u, (unsigned)(cx * 32.f));
        unsigned qy = min(31u, (unsigned)(cy * 32.f));
        unsigned qz = min(31u, (unsigned)(cz * 32.f));
        unsigned key = part5(qx) | (part5(qy) << 1) | (part5(qz) << 2);
        g_keys[slot] = key;
        atomicAdd(&g_hist[key], 1);
    }
}

// ---------------- scan phase A: 64 blocks, local scan of 512 bins -------
__global__ void k_scanA()
{
    __shared__ int wsum[16];
    int b = blockIdx.x;
    int tid = threadIdx.x;            // 128 threads, 4 bins each
    int base = b * 512 + tid * 4;
    int4 c = *(const int4*)&g_hist[base];
    int s = c.x + c.y + c.z + c.w;

    int lane = tid & 31, wid = tid >> 5;
    int v = s;
    #pragma unroll
    for (int d = 1; d < 32; d <<= 1) {
        int t = __shfl_up_sync(0xffffffffu, v, d);
        if (lane >= d) v += t;
    }
    if (lane == 31) wsum[wid] = v;
    __syncthreads();
    if (tid == 0) {
        int acc = 0;
        #pragma unroll
        for (int w = 0; w < 4; w++) { int t = wsum[w]; wsum[w] = acc; acc += t; }
        g_blocksum[b] = acc;
    }
    __syncthreads();
    int excl = v - s + wsum[wid];
    int4 o;
    o.x = excl; o.y = excl + c.x; o.z = o.y + c.y; o.w = o.z + c.z;
    *(int4*)&g_off[base] = o;
}

// ---------------- scan phase B: 64 blocks add block prefixes ------------
__global__ void k_scanB()
{
    __shared__ int pre;
    int b = blockIdx.x;
    int tid = threadIdx.x;            // 128 threads
    if (tid == 0) {
        int acc = 0;
        for (int i = 0; i < b; i++) acc += g_blocksum[i];
        pre = acc;
    }
    __syncthreads();
    int add = pre;
    int4 v = *(int4*)&g_off[b * 512 + tid * 4];
    v.x += add; v.y += add; v.z += add; v.w += add;
    *(int4*)&g_off[b * 512 + tid * 4] = v;
}

// ---------------- scatter into sorted order -----------------------------
__global__ void k_scatter()
{
    int cnt = g_count;
    for (int i = blockIdx.x * blockDim.x + threadIdx.x; i < cnt;
         i += gridDim.x * blockDim.x) {
        float4 p = g_tmp[i];
        unsigned key = g_keys[i];
        int pos = atomicAdd(&g_off[key], 1);
        g_pts[pos] = p;
    }
}

// ---------------- kernel 2: pipelined encode + MLP (fp16 weights) -------
// smem: [w0h 8KB][w1h 8KB][w2 2KB][act 64*BLOCK2*4 = 32KB] = 50.5KB
#define SW0H_OFF 0                       // bytes
#define SW1H_OFF 8192
#define SW2_OFF  16384
#define SACT_OFF 18432
#define SMEM_BYTES (18432 + 64 * BLOCK2 * 4)

__global__ __launch_bounds__(BLOCK2, 3)
void k_encode_mlp(const float* __restrict__ w0,
                  const float* __restrict__ w1,
                  const float* __restrict__ w2,
                  float* __restrict__ out, int N)
{
    extern __shared__ char smc[];
    __half2* sw0h = (__half2*)(smc + SW0H_OFF);   // 2048 half2
    __half2* sw1h = (__half2*)(smc + SW1H_OFF);   // 2048 half2
    float*   sw2  = (float*)(smc + SW2_OFF);      // 512 floats
    float*   sact = (float*)(smc + SACT_OFF);     // 64 * BLOCK2

    int tid = threadIdx.x;
    int cnt = g_count;
    if ((int)(blockIdx.x * BLOCK2) >= cnt) return;

    // stage weights: w0/w1 as fp16 pairs, w2 fp32
    for (int k = tid; k < 2048; k += BLOCK2) {
        float2 a = ((const float2*)w0)[k];
        sw0h[k] = __floats2half2_rn(a.x, a.y);
        float2 b = ((const float2*)w1)[k];
        sw1h[k] = __floats2half2_rn(b.x, b.y);
    }
    for (int k = tid; k < 512 / 4; k += BLOCK2)
        ((float4*)sw2)[k] = ((const float4*)w2)[k];
    __syncthreads();

    const uint2* tbl = (const uint2*)g_tblh;
    float* dxyz = out + N;
    float* drot = out + (size_t)4 * N;

    for (int slot = blockIdx.x * BLOCK2 + tid; slot < cnt;
         slot += gridDim.x * BLOCK2) {
        float4 p = g_pts[slot];
        float cx = p.x, cy = p.y, cz = p.z;
        int ipt = __float_as_int(p.w);

        float h[64];
        #pragma unroll
        for (int j = 0; j < 64; j++) h[j] = 0.f;

        // ---- pipelined encode: issue level-l+1 loads, FMA level-l ----
        uint2 raw[8];
        float cw[8];

        {   // prologue: level 0 loads
            float px = cx * 16.f, py = cy * 16.f, pz = cz * 16.f;
            float fx = floorf(px), fy = floorf(py), fz = floorf(pz);
            float tx = px - fx, ty = py - fy, tz = pz - fz;
            unsigned ux = (unsigned)fx, uy = (unsigned)fy, uz = (unsigned)fz;
            unsigned hx0 = ux,      hx1 = ux + 1u;
            unsigned hy0 = uy * P1, hy1 = hy0 + P1;
            unsigned hz0 = uz * P2, hz1 = hz0 + P2;
            float wxv[2] = {1.f - tx, tx};
            float wyv[2] = {1.f - ty, ty};
            float wzv[2] = {1.f - tz, tz};
            #pragma unroll
            for (int c = 0; c < 8; c++) {
                unsigned hx = (c & 4) ? hx1 : hx0;
                unsigned hy = (c & 2) ? hy1 : hy0;
                unsigned hz = (c & 1) ? hz1 : hz0;
                unsigned idx = (hx ^ hy ^ hz) & TMASK;
                raw[c] = __ldg(tbl + idx);
                cw[c] = wxv[(c >> 2) & 1] * wyv[(c >> 1) & 1] * wzv[c & 1];
            }
        }

        float sc = 32.f;
        #pragma unroll 1
        for (int l = 0; l < L_LEVELS; l++) {
            // 1) consume pending gathers
            float a0 = 0.f, a1 = 0.f, a2 = 0.f, a3 = 0.f;
            #pragma unroll
            for (int c = 0; c < 8; c++) {
                __half2 q01 = *reinterpret_cast<__half2*>(&raw[c].x);
                __half2 q23 = *reinterpret_cast<__half2*>(&raw[c].y);
                float2 f01 = __half22float2(q01);
                float2 f23 = __half22float2(q23);
                float w = cw[c];
                a0 += w * f01.x; a1 += w * f01.y;
                a2 += w * f23.x; a3 += w * f23.y;
            }

            // 2) issue next level's gathers
            if (l + 1 < L_LEVELS) {
                float px = cx * sc, py = cy * sc, pz = cz * sc;
                float fx = floorf(px), fy = floorf(py), fz = floorf(pz);
                float tx = px - fx, ty = py - fy, tz = pz - fz;
                unsigned ux = (unsigned)fx, uy = (unsigned)fy, uz = (unsigned)fz;
                unsigned hx0 = ux,      hx1 = ux + 1u;
                unsigned hy0 = uy * P1, hy1 = hy0 + P1;
                unsigned hz0 = uz * P2, hz1 = hz0 + P2;
                unsigned base = (unsigned)(l + 1) * T_SIZE;
                float wxv[2] = {1.f - tx, tx};
                float wyv[2] = {1.f - ty, ty};
                float wzv[2] = {1.f - tz, tz};
                #pragma unroll
                for (int c = 0; c < 8; c++) {
                    unsigned hx = (c & 4) ? hx1 : hx0;
                    unsigned hy = (c & 2) ? hy1 : hy0;
                    unsigned hz = (c & 1) ? hz1 : hz0;
                    unsigned idx = (hx ^ hy ^ hz) & TMASK;
                    raw[c] = __ldg(tbl + (base + idx));
                    cw[c] = wxv[(c >> 2) & 1] * wyv[(c >> 1) & 1] * wzv[c & 1];
                }
                sc *= 2.f;
            }

            // 3) layer-1 FMA block (fp16 weight rows, 8 halves per LDS.128)
            float av[4] = {a0, a1, a2, a3};
            #pragma unroll
            for (int f = 0; f < 4; f++) {
                const uint4* wr = (const uint4*)(sw0h + ((l * 4 + f) << 5));
                float a = av[f];
                #pragma unroll
                for (int b = 0; b < 8; b++) {
                    uint4 q = wr[b];
                    float2 wv0 = __half22float2(*reinterpret_cast<__half2*>(&q.x));
                    float2 wv1 = __half22float2(*reinterpret_cast<__half2*>(&q.y));
                    float2 wv2 = __half22float2(*reinterpret_cast<__half2*>(&q.z));
                    float2 wv3 = __half22float2(*reinterpret_cast<__half2*>(&q.w));
                    h[8*b+0] += a * wv0.x; h[8*b+1] += a * wv0.y;
                    h[8*b+2] += a * wv1.x; h[8*b+3] += a * wv1.y;
                    h[8*b+4] += a * wv2.x; h[8*b+5] += a * wv2.y;
                    h[8*b+6] += a * wv3.x; h[8*b+7] += a * wv3.y;
                }
            }
        }

        #pragma unroll
        for (int j = 0; j < 64; j++)
            sact[j * BLOCK2 + tid] = fmaxf(h[j], 0.f);

        #pragma unroll
        for (int j = 0; j < 64; j++) h[j] = 0.f;
        #pragma unroll 4
        for (int i = 0; i < 64; i++) {
            float v = sact[i * BLOCK2 + tid];
            const uint4* wr = (const uint4*)(sw1h + (i << 5));
            #pragma unroll
            for (int b = 0; b < 8; b++) {
                uint4 q = wr[b];
                float2 wv0 = __half22float2(*reinterpret_cast<__half2*>(&q.x));
                float2 wv1 = __half22float2(*reinterpret_cast<__half2*>(&q.y));
                float2 wv2 = __half22float2(*reinterpret_cast<__half2*>(&q.z));
                float2 wv3 = __half22float2(*reinterpret_cast<__half2*>(&q.w));
                h[8*b+0] += v * wv0.x; h[8*b+1] += v * wv0.y;
                h[8*b+2] += v * wv1.x; h[8*b+3] += v * wv1.y;
                h[8*b+4] += v * wv2.x; h[8*b+5] += v * wv2.y;
                h[8*b+6] += v * wv3.x; h[8*b+7] += v * wv3.y;
            }
        }
        #pragma unroll
        for (int j = 0; j < 64; j++)
            sact[j * BLOCK2 + tid] = fmaxf(h[j], 0.f);

        float o[8];
        #pragma unroll
        for (int k = 0; k < 8; k++) o[k] = 0.f;
        #pragma unroll 8
        for (int i = 0; i < 64; i++) {
            float v = sact[i * BLOCK2 + tid];
            const float4* wr = (const float4*)(sw2 + (i << 3));
            float4 wa = wr[0], wb = wr[1];
            o[0] += v * wa.x; o[1] += v * wa.y; o[2] += v * wa.z; o[3] += v * wa.w;
            o[4] += v * wb.x; o[5] += v * wb.y; o[6] += v * wb.z; o[7] += v * wb.w;
        }

        dxyz[3 * ipt + 0] = o[0];
        dxyz[3 * ipt + 1] = o[1];
        dxyz[3 * ipt + 2] = o[2];
        drot[4 * ipt + 0] = o[3];
        drot[4 * ipt + 1] = o[4];
        drot[4 * ipt + 2] = o[5];
        drot[4 * ipt + 3] = o[6];
    }
}

// ---------------- launch ----------------
extern "C" void kernel_launch(void* const* d_in, const int* in_sizes, int n_in,
                              void* d_out, int out_size)
{
    const float* xyz   = (const float*)d_in[0];
    const float* bmin  = (const float*)d_in[1];
    const float* bmax  = (const float*)d_in[2];
    const float* table = (const float*)d_in[3];
    const float* w0    = (const float*)d_in[4];
    const float* w1    = (const float*)d_in[5];
    const float* w2    = (const float*)d_in[6];
    int N = in_sizes[0] / 3;
    float* out = (float*)d_out;

    void* cptr = nullptr;
    cudaGetSymbolAddress(&cptr, g_count);
    cudaMemsetAsync(cptr, 0, sizeof(int), 0);
    void* hptr = nullptr;
    cudaGetSymbolAddress(&hptr, g_hist);
    cudaMemsetAsync(hptr, 0, NBINS * sizeof(int), 0);

    int nconv = L_LEVELS * T_SIZE * 4 / 2;
    k_convert<<<(nconv + 255) / 256, 256>>>(table);

    int grid1 = (N + 255) / 256;
    k_mask_compact<<<grid1, 256>>>(xyz, bmin, bmax, out, N);
    k_scanA<<<64, 128>>>();
    k_scanB<<<64, 128>>>();
    k_scatter<<<512, 256>>>();

    cudaFuncSetAttribute(k_encode_mlp,
                         cudaFuncAttributeMaxDynamicSharedMemorySize, SMEM_BYTES);
    k_encode_mlp<<<444, BLOCK2, SMEM_BYTES>>>(w0, w1, w2, out, N);
}